// round 14
// baseline (speedup 1.0000x reference)
#include <cuda_runtime.h>
#include <cuda_bf16.h>
#include <stdint.h>

// Exact Euclidean distance transform (matches the Meijster-style reference)
// on a 1536x1536 binary mask.
//
// Kernel 1 (pack): column-packed background bitmap via warp ballot transpose
//   into a zero-PADDED array (4 guard cols each side, 1 guard word-row
//   top/bottom). colbits[wi][j] bit b == (mask[(wi*32+b)*C + j] == 0).
//   Pads stay zero -> out-of-image probes read "no background", no bounds checks.
//
// Kernel 2 (edt): 4 threads per (column, 32-row word), each owns 8 rows.
//   Flat structure (no smem, no barrier -- the staged R13 variant serialized
//   the loads behind 2 warps and a barrier and was latency-bound at 41% issue).
//   Each thread computes bit-parallel coverage masks for d^2 in {0,1,2,4,5}
//   from 15 bitmap words via OR/funnel-shift (redundant across the quartet;
//   all loads L1/L2-hit), priority-exclusive encodes 3 bit-planes, then emits
//   its 8 rows with a 3-level float-select tree (no I2F/RSQ/LDS per pixel).
//   Rows with d^2 > 5 (P = 2^-21 per pixel for a random mask, ~1 px/image)
//   fall to an exact bitmap walk under a warp vote, reproducing the
//   reference's BIG = R+C cap. Exact for ANY input.
//
// All quantities (g^2 <= 3072^2, t^2, sums < 2^24) are integers exactly
// representable in fp32.

#define R_DIM 1536
#define C_DIM 1536
#define W_DIM (R_DIM / 32)          // 48 word-rows
#define BIG_I (R_DIM + C_DIM)       // 3072
#define CPAD  (C_DIM + 8)           // 4 guard cols each side
#define NROWS (W_DIM + 2)           // 1 guard word-row top/bottom

__device__ uint32_t g_colbits[NROWS * CPAD];   // zero-initialized; pads stay 0

__device__ __forceinline__ const uint32_t* cb_at(int wi, int j) {
    return &g_colbits[(wi + 1) * CPAD + 4 + j];
}

// 8 warps/block, each warp packs one 32x32 tile. grid(6, 48).
__global__ __launch_bounds__(256) void pack_kernel(const float* __restrict__ mask)
{
    const int lane = threadIdx.x & 31;
    const int warp = threadIdx.x >> 5;
    const int col0 = (blockIdx.x * 8 + warp) * 32;
    const int row0 = blockIdx.y * 32;

    const float* p = mask + row0 * C_DIM + col0 + lane;

    float v[32];
    #pragma unroll
    for (int r = 0; r < 32; ++r) v[r] = p[r * C_DIM];

    uint32_t myword = 0;
    #pragma unroll
    for (int r = 0; r < 32; ++r) {
        const uint32_t b = __ballot_sync(0xffffffffu, v[r] == 0.0f);
        myword |= ((b >> lane) & 1u) << r;
    }
    g_colbits[(blockIdx.y + 1) * CPAD + 4 + col0 + lane] = myword;
}

// Exact vertical distance^2 at (r, k) from the bitmap (rare path).
__device__ __noinline__ int g2_global(int r, int k)
{
    const int wi = r >> 5, bi = r & 31;
    const uint32_t w = *cb_at(wi, k);
    int best = BIG_I;
    const uint32_t dn = w >> bi;
    if (dn) best = __ffs(dn) - 1;
    const uint32_t up = w << (31 - bi);
    if (up) best = min(best, __clz(up));
    int wd = wi + 1, dn_off = 32 - bi;
    int wu = wi - 1, up_off = bi + 1;
    while ((wd < W_DIM && dn_off < best) || (wu >= 0 && up_off < best)) {
        if (wd < W_DIM && dn_off < best) {
            const uint32_t x = *cb_at(wd, k);
            if (x) best = min(best, dn_off + __ffs(x) - 1);
            ++wd; dn_off += 32;
        } else wd = W_DIM;
        if (wu >= 0 && up_off < best) {
            const uint32_t x = *cb_at(wu, k);
            if (x) best = min(best, up_off + __clz(x));
            --wu; up_off += 32;
        } else wu = -1;
    }
    return best * best;
}

// vertical +/-k shift across word boundaries: bit b set if (row +- k) set
__device__ __forceinline__ uint32_t sv(uint32_t w, uint32_t prev, uint32_t next, int k)
{
    return __funnelshift_r(w, next, k) | __funnelshift_l(prev, w, k);
}

// 256 threads = 64 columns x 4 row-quarters. grid(24, 48).
__global__ __launch_bounds__(256) void edt_kernel(float* __restrict__ out)
{
    const int tid = threadIdx.x;
    const int j   = blockIdx.x * 64 + (tid & 63);
    const int q   = tid >> 6;            // row-quarter 0..3
    const int sh  = q * 8;
    const int wi  = blockIdx.y;

    const uint32_t* W = cb_at(wi, j);
    const uint32_t* P = W - CPAD;
    const uint32_t* N = W + CPAD;

    // 15 word loads (pads make all of them branch-free; L1-hit, shared by quartet)
    const uint32_t c0 = W[0];
    const uint32_t c1 = W[-1] | W[1];
    const uint32_t c2 = W[-2] | W[2];
    const uint32_t p0 = P[0];
    const uint32_t p1 = P[-1] | P[1];
    const uint32_t p2 = P[-2] | P[2];
    const uint32_t n0 = N[0];
    const uint32_t n1 = N[-1] | N[1];
    const uint32_t n2 = N[-2] | N[2];

    // coverage masks per d^2 level (32 rows at once)
    const uint32_t D1 = sv(c0, p0, n0, 1) | c1;
    const uint32_t D2 = sv(c1, p1, n1, 1);
    const uint32_t D4 = sv(c0, p0, n0, 2) | c2;
    const uint32_t D5 = sv(c1, p1, n1, 2) | sv(c2, p2, n2, 1);

    // priority-exclusive -> 3 bit-planes (d^2 <= 5); uncovered -> index 7
    uint32_t cum = c0;
    const uint32_t E1 = D1 & ~cum;  cum |= D1;
    const uint32_t E2 = D2 & ~cum;  cum |= D2;
    const uint32_t E4 = D4 & ~cum;  cum |= D4;
    const uint32_t E5 = D5 & ~cum;  cum |= D5;
    const uint32_t un = ~cum;

    const uint32_t b0 = (E1 | E5 | un) >> sh;
    const uint32_t b1 = (E2 | un) >> sh;
    const uint32_t b2 = (E4 | E5 | un) >> sh;

    float* orow = out + (wi * 32 + sh) * C_DIM + j;
    #pragma unroll
    for (int r = 0; r < 8; ++r) {
        const bool t0 = (b0 >> r) & 1;
        const bool t1 = (b1 >> r) & 1;
        const bool t2 = (b2 >> r) & 1;
        // idx 0->0, 1->1, 2->sqrt2, 4->2, 5->sqrt5 (7 overwritten by fallback)
        const float hi = t0 ? 2.23606798f : 2.0f;
        const float lo = t1 ? 1.41421356f : (t0 ? 1.0f : 0.0f);
        orow[r * C_DIM] = t2 ? hi : lo;
    }

    // exact fallback for rows with d^2 > 5 (~1 pixel per image)
    const uint32_t uncov8 = un >> sh & 0xffu;
    if (__any_sync(0xffffffffu, uncov8 != 0u)) {
        uint32_t uncov = uncov8;
        while (uncov) {
            const int b = __ffs(uncov) - 1;
            uncov &= uncov - 1;
            const int row = wi * 32 + sh + b;
            int best = g2_global(row, j);
            int t = 1, t2i = 1, inc = 3;
            while (t2i < best) {
                const int kl = j - t, kr = j + t;
                if (kl < 0 && kr >= C_DIM) break;
                if (kl >= 0)     best = min(best, g2_global(row, kl) + t2i);
                if (kr < C_DIM)  best = min(best, g2_global(row, kr) + t2i);
                t2i += inc; inc += 2; ++t;
            }
            const float f = (float)best;
            orow[b * C_DIM] = best ? f * __frsqrt_rn(f) : 0.0f;
        }
    }
}

extern "C" void kernel_launch(void* const* d_in, const int* in_sizes, int n_in,
                              void* d_out, int out_size) {
    const float* mask = (const float*)d_in[0];
    float* out = (float*)d_out;

    dim3 pgrid(C_DIM / 256, R_DIM / 32);   // (6, 48)
    pack_kernel<<<pgrid, 256>>>(mask);

    dim3 egrid(C_DIM / 64, W_DIM);         // (24, 48)
    edt_kernel<<<egrid, 256>>>(out);
}